// round 8
// baseline (speedup 1.0000x reference)
#include <cuda_runtime.h>
#include <cuda_fp16.h>
#include <cstdint>

// ============================================================================
// LSTM decoder, B=2048, T=32, H=1024, inference path (pred feedback).
// sm_100: fp16 mma.sync GEMM + cp.async 3-stage pipeline, 2 CTAs/SM.
//
// Per step: D[2048,4096] = A[2048,1024](fp16 h) * W[4096,1024]^T (fp16)
// R8: register shuffle-exchange epilogue (no gates smem round-trip, no
// epilogue barriers) — the smem crossbar is co-saturated with the HMMA pipe
// (R7 finding), so epilogue smem traffic was on the critical resource.
// W columns permuted: col n -> (unit n>>2, gate n&3), gate order i,f,g,o.
// One kernel launch per time step = grid-wide dependency barrier.
// h double-buffered across steps (cross-CTA race fix).
// ============================================================================

#define BATCH 2048
#define TT    32
#define HH    1024
#define N4    4096
#define KE    1024            // K = H (single fp16 term)
#define TM    128             // M tile
#define TN    128             // N tile
#define KC    64              // K chunk (fp16) = 128 bytes
#define NCH   (KE / KC)       // 16
#define NTHREADS 256
#define STAGES 3
#define STAGE_BYTES 32768     // A 16KB + B 16KB
#define STAGING_BYTES 2048    // bias/w0/w1 float4[32] + fcW float[32]
#define SMEM_BYTES  (1024 + STAGES * STAGE_BYTES + STAGING_BYTES)   // ~101KB -> 2 CTAs/SM

// Scratch (device globals; no allocation allowed)
__device__ __align__(256) __half g_Wext[(size_t)N4 * KE];        // 8 MB
__device__ __align__(256) __half g_Aext[2][(size_t)BATCH * KE];  // 2 x 4 MB
__device__ __align__(256) float g_c[(size_t)BATCH * HH];         // 8 MB
__device__ __align__(256) float g_predsum[BATCH * TT];
__device__ __align__(256) float g_bias[N4];
__device__ __align__(256) float g_w0[N4];
__device__ __align__(256) float g_w1[N4];
__device__ __align__(256) float g_fcW[HH];

// ---------------------------------------------------------------------------
// helpers
// ---------------------------------------------------------------------------
__device__ __forceinline__ uint32_t smem_u32(const void* p) {
    uint32_t a;
    asm("{ .reg .u64 t; cvta.to.shared.u64 t, %1; cvt.u32.u64 %0, t; }" : "=r"(a) : "l"(p));
    return a;
}
__device__ __forceinline__ void cp_async16(uint32_t dst, const void* src) {
    asm volatile("cp.async.cg.shared.global [%0], [%1], 16;" :: "r"(dst), "l"(src) : "memory");
}
__device__ __forceinline__ void cp_commit() {
    asm volatile("cp.async.commit_group;" ::: "memory");
}
__device__ __forceinline__ uint32_t sw128(uint32_t off) {
    return off ^ ((off >> 3) & 0x70u);
}
__device__ __forceinline__ void ldsm_x4(uint32_t& r0, uint32_t& r1, uint32_t& r2, uint32_t& r3,
                                        uint32_t addr) {
    asm volatile("ldmatrix.sync.aligned.m8n8.x4.shared.b16 {%0,%1,%2,%3}, [%4];"
                 : "=r"(r0), "=r"(r1), "=r"(r2), "=r"(r3) : "r"(addr));
}
__device__ __forceinline__ void mma_fp16(float* d, const uint32_t* a, const uint32_t* b) {
    asm volatile(
        "mma.sync.aligned.m16n8k16.row.col.f32.f16.f16.f32 "
        "{%0,%1,%2,%3}, {%4,%5,%6,%7}, {%8,%9}, {%0,%1,%2,%3};"
        : "+f"(d[0]), "+f"(d[1]), "+f"(d[2]), "+f"(d[3])
        : "r"(a[0]), "r"(a[1]), "r"(a[2]), "r"(a[3]), "r"(b[0]), "r"(b[1]));
}
__device__ __forceinline__ float sigf(float x) {
    return __fdividef(1.0f, 1.0f + __expf(-x));
}
__device__ __forceinline__ float tanh_f(float x) {
    float xc = fminf(fmaxf(x, -15.0f), 15.0f);
    float e = __expf(2.0f * xc);
    return 1.0f - __fdividef(2.0f, e + 1.0f);
}

// ---------------------------------------------------------------------------
// Prep kernels
// ---------------------------------------------------------------------------
__global__ void prep_weights(const float* __restrict__ W_hh, const float* __restrict__ W_ih,
                             const float* __restrict__ b_ih, const float* __restrict__ b_hh,
                             const float* __restrict__ fc_W) {
    int idx = blockIdx.x * blockDim.x + threadIdx.x;   // 0 .. 4096*1024-1
    int n = idx >> 10, k = idx & 1023;
    int r = (n & 3) * HH + (n >> 2);                   // col n -> orig W_hh row
    g_Wext[(size_t)n * KE + k] = __float2half(W_hh[(size_t)r * HH + k]);
    if (idx < N4) {
        int rr = (idx & 3) * HH + (idx >> 2);
        g_bias[idx] = b_ih[rr] + b_hh[rr];
        g_w0[idx] = W_ih[rr * 2 + 0];
        g_w1[idx] = W_ih[rr * 2 + 1];
    }
    if (idx < HH) g_fcW[idx] = fc_W[idx];
}

__global__ void prep_state(const float* __restrict__ hidden, const float* __restrict__ cell) {
    int idx = blockIdx.x * blockDim.x + threadIdx.x;   // 0 .. 2048*1024-1
    g_c[idx] = cell[idx];
    g_Aext[0][idx] = __float2half(hidden[idx]);
    if (idx < BATCH * TT) g_predsum[idx] = 0.0f;
}

__global__ void finalize_out(float* __restrict__ out, const float* __restrict__ fc_b) {
    int idx = blockIdx.x * blockDim.x + threadIdx.x;
    if (idx < BATCH * TT) out[idx] = g_predsum[idx] + fc_b[0];
}

// ---------------------------------------------------------------------------
// Step kernel: GEMM (tile 128x128, K=1024) + register-exchange LSTM epilogue
// 256 threads = 8 warps; warp tile 64x32: warp_m = wid&1, warp_n = wid>>1.
// ---------------------------------------------------------------------------
__global__ void __launch_bounds__(NTHREADS, 2)
step_kernel(int t, const float* __restrict__ future_fd, const float* __restrict__ fc_b) {
    const __half* __restrict__ Asrc = g_Aext[t & 1];
    __half* __restrict__ Adst = g_Aext[(t + 1) & 1];

    extern __shared__ char smem_raw[];
    uint32_t sb = smem_u32(smem_raw);
    uint32_t ab = (sb + 1023u) & ~1023u;
    char* smem = smem_raw + (ab - sb);
    const uint32_t tiles = ab;

    const int tid = threadIdx.x;
    const int wid = tid >> 5;
    const int lid = tid & 31;
    const int wm = wid & 1;          // 0..1  (64-row block)
    const int wn = wid >> 1;         // 0..3  (32-col block)
    const int m0 = blockIdx.x * TM;
    const int n0 = blockIdx.y * TN;
    const int u0 = n0 >> 2;          // first unit of this CTA (32 units total)

    // ---- staging: bias/w0/w1 as float4 per unit, fcW per unit --------------
    float4* smB  = (float4*)(smem + STAGES * STAGE_BYTES);   // [32]
    float4* smW0 = smB + 32;                                  // [32]
    float4* smW1 = smB + 64;                                  // [32]
    float*  smFc = (float*)(smB + 96);                        // [32]
    if (tid < 32)        smB[tid]        = ((const float4*)g_bias)[u0 + tid];
    else if (tid < 64)   smW0[tid - 32]  = ((const float4*)g_w0)[u0 + tid - 32];
    else if (tid < 96)   smW1[tid - 64]  = ((const float4*)g_w1)[u0 + tid - 64];
    else if (tid < 128)  smFc[tid - 96]  = g_fcW[u0 + tid - 96];
    // visibility: first mainloop __syncthreads covers it

    // ---- chunk loader: 256 rows x 128B (A rows 0..127, B rows 0..127) ------
    auto load_chunk = [&](int c, int s) {
        const int k0 = c * KC;
        const uint32_t base = tiles + s * STAGE_BYTES;
        #pragma unroll
        for (int j = 0; j < 8; j++) {
            int li = tid + j * NTHREADS;
            int ri = li >> 3, q = li & 7;
            if (ri < TM) {
                uint32_t dst = base + sw128((uint32_t)(ri * 128 + q * 16));
                cp_async16(dst, Asrc + ((size_t)(m0 + ri) * KE + k0 + q * 8));
            } else {
                int rb = ri - TM;
                uint32_t dst = base + 16384 + sw128((uint32_t)(rb * 128 + q * 16));
                cp_async16(dst, g_Wext + ((size_t)(n0 + rb) * KE + k0 + q * 8));
            }
        }
        cp_commit();
    };

    // ---- lane constants for ldmatrix addressing ----------------------------
    const int a_lr = lid & 15;
    const int a_ch = (lid >> 4) << 4;
    const int b_nr = (lid & 7) + ((lid >> 4) << 3);
    const int b_ch = ((lid >> 3) & 1) << 4;

    float acc[4][4][4];
    #pragma unroll
    for (int i = 0; i < 4; i++)
        #pragma unroll
        for (int j = 0; j < 4; j++)
            #pragma unroll
            for (int r = 0; r < 4; r++) acc[i][j][r] = 0.0f;

    load_chunk(0, 0);
    load_chunk(1, 1);

    #pragma unroll 1
    for (int c = 0; c < NCH; c++) {
        if (c < NCH - 2) asm volatile("cp.async.wait_group 1;" ::: "memory");
        else             asm volatile("cp.async.wait_group 0;" ::: "memory");
        __syncthreads();

        if (c + 2 < NCH) load_chunk(c + 2, (c + 2) % STAGES);

        const uint32_t As = tiles + (c % STAGES) * STAGE_BYTES;
        const uint32_t Bs = As + 16384;

        #pragma unroll
        for (int ks = 0; ks < 4; ks++) {
            uint32_t a[4][4], b[4][2];
            #pragma unroll
            for (int mi = 0; mi < 4; mi++) {
                uint32_t off = (uint32_t)((wm * 64 + mi * 16 + a_lr) * 128 + ks * 32 + a_ch);
                ldsm_x4(a[mi][0], a[mi][1], a[mi][2], a[mi][3], As + sw128(off));
            }
            #pragma unroll
            for (int nb = 0; nb < 2; nb++) {
                uint32_t off = (uint32_t)((wn * 32 + nb * 16 + b_nr) * 128 + ks * 32 + b_ch);
                ldsm_x4(b[nb * 2][0], b[nb * 2][1], b[nb * 2 + 1][0], b[nb * 2 + 1][1],
                        Bs + sw128(off));
            }
            #pragma unroll
            for (int mi = 0; mi < 4; mi++)
                #pragma unroll
                for (int j = 0; j < 4; j++)
                    mma_fp16(acc[mi][j], a[mi], b[j]);
        }
    }

    // ---- register shuffle-exchange epilogue (no barriers, no gates smem) ---
    // Fragment map (m16n8k16): lane = 4*g + tg (g=0..7, tg=0..3).
    //   acc[mi][j][0..1] = row (wm*64+mi*16+g),   cols (wn*32+j*8) + {2tg, 2tg+1}
    //   acc[mi][j][2..3] = row (+8),              same cols
    // Per 8-col block j: units U=2j (tg0: gates i,f; tg1: g,o) and
    // U+1 (tg2: i,f; tg3: g,o). Partner lane = lid^1.
    // After exchange: tg even -> all 4 gates of its unit, row g;
    //                 tg odd  -> all 4 gates of its unit, row g+8.
    const int g  = lid >> 2, tg = lid & 3;
    const bool even = (tg & 1) == 0;
    const float fcb = fc_b[0];

    #pragma unroll
    for (int mi = 0; mi < 4; mi++) {
        const int r = wm * 64 + mi * 16 + g + ((tg & 1) ? 8 : 0);
        const int b = m0 + r;
        float prev = 0.0f;
        if (t > 0) prev = g_predsum[b * TT + (t - 1)] + fcb;
        const float fdv = future_fd[b * TT + t];
        float fcacc = 0.0f;

        #pragma unroll
        for (int j = 0; j < 4; j++) {
            float sa = even ? acc[mi][j][2] : acc[mi][j][0];
            float sb2 = even ? acc[mi][j][3] : acc[mi][j][1];
            float ra = __shfl_xor_sync(0xFFFFFFFFu, sa, 1);
            float rb = __shfl_xor_sync(0xFFFFFFFFu, sb2, 1);
            float gi = even ? acc[mi][j][0] : ra;
            float gf = even ? acc[mi][j][1] : rb;
            float gg = even ? ra : acc[mi][j][2];
            float go = even ? rb : acc[mi][j][3];

            const int ul = wn * 8 + j * 2 + (tg >> 1);   // local unit 0..31
            const int ug = u0 + ul;                       // global unit
            float4 bs = smB[ul];
            float4 w0 = smW0[ul];
            float4 w1 = smW1[ul];

            gi += bs.x + prev * w0.x + fdv * w1.x;
            gf += bs.y + prev * w0.y + fdv * w1.y;
            gg += bs.z + prev * w0.z + fdv * w1.z;
            go += bs.w + prev * w0.w + fdv * w1.w;

            float co = g_c[(size_t)b * HH + ug];
            float cn = sigf(gf) * co + sigf(gi) * tanh_f(gg);
            float h  = sigf(go) * tanh_f(cn);
            g_c[(size_t)b * HH + ug] = cn;
            Adst[(size_t)b * KE + ug] = __float2half(h);
            fcacc += h * smFc[ul];
        }
        // lanes lid^2 share the same row, complementary units
        fcacc += __shfl_xor_sync(0xFFFFFFFFu, fcacc, 2);
        if (tg < 2) atomicAdd(&g_predsum[b * TT + t], fcacc);
    }
}

// ---------------------------------------------------------------------------
// Host launcher
// ---------------------------------------------------------------------------
extern "C" void kernel_launch(void* const* d_in, const int* in_sizes, int n_in,
                              void* d_out, int out_size) {
    const float* future_fd = (const float*)d_in[0];
    const float* hidden    = (const float*)d_in[1];
    const float* cell      = (const float*)d_in[2];
    const float* W_ih      = (const float*)d_in[3];
    const float* W_hh      = (const float*)d_in[4];
    const float* b_ih      = (const float*)d_in[5];
    const float* b_hh      = (const float*)d_in[6];
    const float* fc_W      = (const float*)d_in[7];
    const float* fc_b      = (const float*)d_in[8];

    cudaFuncSetAttribute(step_kernel, cudaFuncAttributeMaxDynamicSharedMemorySize, SMEM_BYTES);

    prep_weights<<<(N4 * HH) / 256, 256>>>(W_hh, W_ih, b_ih, b_hh, fc_W);
    prep_state<<<(BATCH * HH) / 256, 256>>>(hidden, cell);
    for (int t = 0; t < TT; t++) {
        step_kernel<<<dim3(BATCH / TM, N4 / TN), NTHREADS, SMEM_BYTES>>>(t, future_fd, fc_b);
    }
    finalize_out<<<(BATCH * TT + 255) / 256, 256>>>((float*)d_out, fc_b);
}

// round 9
// speedup vs baseline: 1.6844x; 1.6844x over previous
#include <cuda_runtime.h>
#include <cuda_fp16.h>
#include <cstdint>

// ============================================================================
// LSTM decoder, B=2048, T=32, H=1024, inference path (pred feedback).
// sm_100: fp16 mma.sync GEMM + cp.async 3-stage pipeline.
//
// Per step: D[2048,4096] = A[2048,1024](fp16 h) * W[4096,1024]^T (fp16)
// R9: warp tile 64x64 (8 warps, CTA 128x256, 1 CTA/SM). Scaling law from
// R3-R8: achieved TFLOPs track MAC/smem-byte; 64x64 warp tile gives ldsm
// ratio 16 MAC/B (vs 10.67 at 64x32), making the kernel tensor-bound.
// Epilogue: proven R4 two-half smem-gates scheme (coalesced).
// W columns permuted: col n -> (unit n>>2, gate n&3), gate order i,f,g,o.
// One kernel launch per time step = grid-wide dependency barrier.
// h double-buffered across steps (cross-CTA race fix).
// ============================================================================

#define BATCH 2048
#define TT    32
#define HH    1024
#define N4    4096
#define KE    1024            // K = H (single fp16 term)
#define TM    128             // M tile
#define TN    256             // N tile
#define KC    64              // K chunk (fp16) = 128 bytes
#define NCH   (KE / KC)       // 16
#define NTHREADS 256
#define STAGES 3
#define STAGE_BYTES 49152     // A 16KB + B 32KB
#define SMEM_BYTES  (1024 + STAGES * STAGE_BYTES)   // 148480
#define GPITCH 132            // gates smem pitch (floats), proven R4

// Scratch (device globals; no allocation allowed)
__device__ __align__(256) __half g_Wext[(size_t)N4 * KE];        // 8 MB
__device__ __align__(256) __half g_Aext[2][(size_t)BATCH * KE];  // 2 x 4 MB
__device__ __align__(256) float g_c[(size_t)BATCH * HH];         // 8 MB
__device__ __align__(256) float g_predsum[BATCH * TT];
__device__ __align__(256) float g_bias[N4];
__device__ __align__(256) float g_w0[N4];
__device__ __align__(256) float g_w1[N4];
__device__ __align__(256) float g_fcW[HH];

// ---------------------------------------------------------------------------
// helpers
// ---------------------------------------------------------------------------
__device__ __forceinline__ uint32_t smem_u32(const void* p) {
    uint32_t a;
    asm("{ .reg .u64 t; cvta.to.shared.u64 t, %1; cvt.u32.u64 %0, t; }" : "=r"(a) : "l"(p));
    return a;
}
__device__ __forceinline__ void cp_async16(uint32_t dst, const void* src) {
    asm volatile("cp.async.cg.shared.global [%0], [%1], 16;" :: "r"(dst), "l"(src) : "memory");
}
__device__ __forceinline__ void cp_commit() {
    asm volatile("cp.async.commit_group;" ::: "memory");
}
__device__ __forceinline__ uint32_t sw128(uint32_t off) {
    return off ^ ((off >> 3) & 0x70u);
}
__device__ __forceinline__ void ldsm_x4(uint32_t& r0, uint32_t& r1, uint32_t& r2, uint32_t& r3,
                                        uint32_t addr) {
    asm volatile("ldmatrix.sync.aligned.m8n8.x4.shared.b16 {%0,%1,%2,%3}, [%4];"
                 : "=r"(r0), "=r"(r1), "=r"(r2), "=r"(r3) : "r"(addr));
}
__device__ __forceinline__ void mma_fp16(float* d, const uint32_t* a, const uint32_t* b) {
    asm volatile(
        "mma.sync.aligned.m16n8k16.row.col.f32.f16.f16.f32 "
        "{%0,%1,%2,%3}, {%4,%5,%6,%7}, {%8,%9}, {%0,%1,%2,%3};"
        : "+f"(d[0]), "+f"(d[1]), "+f"(d[2]), "+f"(d[3])
        : "r"(a[0]), "r"(a[1]), "r"(a[2]), "r"(a[3]), "r"(b[0]), "r"(b[1]));
}
__device__ __forceinline__ float sigf(float x) {
    return __fdividef(1.0f, 1.0f + __expf(-x));
}
__device__ __forceinline__ float tanh_f(float x) {
    float xc = fminf(fmaxf(x, -15.0f), 15.0f);
    float e = __expf(2.0f * xc);
    return 1.0f - __fdividef(2.0f, e + 1.0f);
}

// ---------------------------------------------------------------------------
// Prep kernels
// ---------------------------------------------------------------------------
__global__ void prep_weights(const float* __restrict__ W_hh, const float* __restrict__ W_ih,
                             const float* __restrict__ b_ih, const float* __restrict__ b_hh,
                             const float* __restrict__ fc_W) {
    int idx = blockIdx.x * blockDim.x + threadIdx.x;   // 0 .. 4096*1024-1
    int n = idx >> 10, k = idx & 1023;
    int r = (n & 3) * HH + (n >> 2);                   // col n -> orig W_hh row
    g_Wext[(size_t)n * KE + k] = __float2half(W_hh[(size_t)r * HH + k]);
    if (idx < N4) {
        int rr = (idx & 3) * HH + (idx >> 2);
        g_bias[idx] = b_ih[rr] + b_hh[rr];
        g_w0[idx] = W_ih[rr * 2 + 0];
        g_w1[idx] = W_ih[rr * 2 + 1];
    }
    if (idx < HH) g_fcW[idx] = fc_W[idx];
}

__global__ void prep_state(const float* __restrict__ hidden, const float* __restrict__ cell) {
    int idx = blockIdx.x * blockDim.x + threadIdx.x;   // 0 .. 2048*1024-1
    g_c[idx] = cell[idx];
    g_Aext[0][idx] = __float2half(hidden[idx]);
    if (idx < BATCH * TT) g_predsum[idx] = 0.0f;
}

__global__ void finalize_out(float* __restrict__ out, const float* __restrict__ fc_b) {
    int idx = blockIdx.x * blockDim.x + threadIdx.x;
    if (idx < BATCH * TT) out[idx] = g_predsum[idx] + fc_b[0];
}

// ---------------------------------------------------------------------------
// Step kernel: GEMM (tile 128x256, K=1024) + fused LSTM cell epilogue
// 256 threads = 8 warps; warp tile 64x64: warp_m = wid&1, warp_n = wid>>1.
// ---------------------------------------------------------------------------
__global__ void __launch_bounds__(NTHREADS, 1)
step_kernel(int t, const float* __restrict__ future_fd, const float* __restrict__ fc_b) {
    const __half* __restrict__ Asrc = g_Aext[t & 1];
    __half* __restrict__ Adst = g_Aext[(t + 1) & 1];

    extern __shared__ char smem_raw[];
    uint32_t sb = smem_u32(smem_raw);
    uint32_t ab = (sb + 1023u) & ~1023u;
    char* smem = smem_raw + (ab - sb);
    const uint32_t tiles = ab;

    const int tid = threadIdx.x;
    const int wid = tid >> 5;
    const int lid = tid & 31;
    const int wm = wid & 1;          // 0..1  (64-row block)
    const int wn = wid >> 1;         // 0..3  (64-col block)
    const int m0 = blockIdx.x * TM;
    const int n0 = blockIdx.y * TN;

    // ---- chunk loader: 384 rows x 128B (A rows 0..127, B rows 0..255) ------
    auto load_chunk = [&](int c, int s) {
        const int k0 = c * KC;
        const uint32_t base = tiles + s * STAGE_BYTES;
        #pragma unroll
        for (int j = 0; j < 12; j++) {
            int li = tid + j * NTHREADS;   // 0..3071
            int ri = li >> 3, q = li & 7;
            if (ri < TM) {
                uint32_t dst = base + sw128((uint32_t)(ri * 128 + q * 16));
                cp_async16(dst, Asrc + ((size_t)(m0 + ri) * KE + k0 + q * 8));
            } else {
                int rb = ri - TM;          // 0..255
                uint32_t dst = base + 16384 + sw128((uint32_t)(rb * 128 + q * 16));
                cp_async16(dst, g_Wext + ((size_t)(n0 + rb) * KE + k0 + q * 8));
            }
        }
        cp_commit();
    };

    // ---- lane constants for ldmatrix addressing ----------------------------
    const int a_lr = lid & 15;                      // A row within 16
    const int a_ch = (lid >> 4) << 4;               // A k-byte offset (0/16)
    const int b_nr = (lid & 7) + ((lid >> 4) << 3); // B n-row within 16
    const int b_ch = ((lid >> 3) & 1) << 4;         // B k-byte offset (0/16)

    float acc[4][8][4];
    #pragma unroll
    for (int i = 0; i < 4; i++)
        #pragma unroll
        for (int j = 0; j < 8; j++)
            #pragma unroll
            for (int r = 0; r < 4; r++) acc[i][j][r] = 0.0f;

    load_chunk(0, 0);
    load_chunk(1, 1);

    #pragma unroll 1
    for (int c = 0; c < NCH; c++) {
        if (c < NCH - 2) asm volatile("cp.async.wait_group 1;" ::: "memory");
        else             asm volatile("cp.async.wait_group 0;" ::: "memory");
        __syncthreads();

        if (c + 2 < NCH) load_chunk(c + 2, (c + 2) % STAGES);

        const uint32_t As = tiles + (c % STAGES) * STAGE_BYTES;
        const uint32_t Bs = As + 16384;

        #pragma unroll
        for (int ks = 0; ks < 4; ks++) {
            uint32_t a[4][4], b[8][2];
            #pragma unroll
            for (int mi = 0; mi < 4; mi++) {
                uint32_t off = (uint32_t)((wm * 64 + mi * 16 + a_lr) * 128 + ks * 32 + a_ch);
                ldsm_x4(a[mi][0], a[mi][1], a[mi][2], a[mi][3], As + sw128(off));
            }
            #pragma unroll
            for (int nb = 0; nb < 4; nb++) {
                uint32_t off = (uint32_t)((wn * 64 + nb * 16 + b_nr) * 128 + ks * 32 + b_ch);
                ldsm_x4(b[nb * 2][0], b[nb * 2][1], b[nb * 2 + 1][0], b[nb * 2 + 1][1],
                        Bs + sw128(off));
            }
            #pragma unroll
            for (int mi = 0; mi < 4; mi++)
                #pragma unroll
                for (int j = 0; j < 8; j++)
                    mma_fp16(acc[mi][j], a[mi], b[j]);
        }
    }
    __syncthreads();   // smem stages now reusable as epilogue scratch

    // ---- epilogue: gates -> smem (two 128-col halves), fused cell update ---
    float* gates = (float*)smem;                  // 128 rows x GPITCH floats
    const int g = lid >> 2, tg = lid & 3;
    const float fcb = fc_b[0];

    #pragma unroll 1
    for (int half = 0; half < 2; half++) {
        if ((wn >> 1) == half) {
            const int clb = (wn & 1) * 64;
            #pragma unroll
            for (int mi = 0; mi < 4; mi++) {
                const int r = wm * 64 + mi * 16 + g;
                #pragma unroll
                for (int j = 0; j < 8; j++) {
                    const int cl = clb + j * 8 + 2 * tg;
                    *(float2*)&gates[r * GPITCH + cl] =
                        make_float2(acc[mi][j][0], acc[mi][j][1]);
                    *(float2*)&gates[(r + 8) * GPITCH + cl] =
                        make_float2(acc[mi][j][2], acc[mi][j][3]);
                }
            }
        }
        __syncthreads();

        #pragma unroll 1
        for (int jj = 0; jj < 16; jj++) {
            const int idx = tid + jj * NTHREADS;       // 4096 = 128 rows x 32 units
            const int row = idx >> 5, u = idx & 31;
            const int n = n0 + half * 128 + 4 * u;
            const int ug = n >> 2;                     // global unit 0..1023
            const int b = m0 + row;

            float4 gv = *(float4*)&gates[row * GPITCH + 4 * u];
            float4 bs = ((const float4*)g_bias)[n >> 2];
            float4 w0 = ((const float4*)g_w0)[n >> 2];
            float4 w1 = ((const float4*)g_w1)[n >> 2];

            float prev = 0.0f;
            if (t > 0) prev = g_predsum[b * TT + (t - 1)] + fcb;
            const float fdv = future_fd[b * TT + t];

            float gi = gv.x + bs.x + prev * w0.x + fdv * w1.x;
            float gf = gv.y + bs.y + prev * w0.y + fdv * w1.y;
            float gg = gv.z + bs.z + prev * w0.z + fdv * w1.z;
            float go = gv.w + bs.w + prev * w0.w + fdv * w1.w;

            float co = g_c[(size_t)b * HH + ug];
            float cn = sigf(gf) * co + sigf(gi) * tanh_f(gg);
            float h  = sigf(go) * tanh_f(cn);
            g_c[(size_t)b * HH + ug] = cn;
            Adst[(size_t)b * KE + ug] = __float2half(h);

            float fcp = h * g_fcW[ug];
            #pragma unroll
            for (int o = 16; o; o >>= 1) fcp += __shfl_down_sync(0xFFFFFFFFu, fcp, o);
            if (lid == 0) atomicAdd(&g_predsum[b * TT + t], fcp);
        }
        __syncthreads();
    }
}

// ---------------------------------------------------------------------------
// Host launcher
// ---------------------------------------------------------------------------
extern "C" void kernel_launch(void* const* d_in, const int* in_sizes, int n_in,
                              void* d_out, int out_size) {
    const float* future_fd = (const float*)d_in[0];
    const float* hidden    = (const float*)d_in[1];
    const float* cell      = (const float*)d_in[2];
    const float* W_ih      = (const float*)d_in[3];
    const float* W_hh      = (const float*)d_in[4];
    const float* b_ih      = (const float*)d_in[5];
    const float* b_hh      = (const float*)d_in[6];
    const float* fc_W      = (const float*)d_in[7];
    const float* fc_b      = (const float*)d_in[8];

    cudaFuncSetAttribute(step_kernel, cudaFuncAttributeMaxDynamicSharedMemorySize, SMEM_BYTES);

    prep_weights<<<(N4 * HH) / 256, 256>>>(W_hh, W_ih, b_ih, b_hh, fc_W);
    prep_state<<<(BATCH * HH) / 256, 256>>>(hidden, cell);
    for (int t = 0; t < TT; t++) {
        step_kernel<<<dim3(BATCH / TM, N4 / TN), NTHREADS, SMEM_BYTES>>>(t, future_fd, fc_b);
    }
    finalize_out<<<(BATCH * TT + 255) / 256, 256>>>((float*)d_out, fc_b);
}

// round 10
// speedup vs baseline: 2.1157x; 1.2561x over previous
#include <cuda_runtime.h>
#include <cuda_fp16.h>
#include <cstdint>

// ============================================================================
// LSTM decoder, B=2048, T=32, H=1024, inference path (pred feedback).
// sm_100: fp16 mma.sync GEMM + cp.async 3-stage pipeline, 2 CTAs/SM (R5
// champion config) + R10 overhead cuts:
//  - PDL: steps t>=1 launch early, prefetch W chunks + const staging before
//    griddepcontrol.wait; A (h) loads after. launch_dependents after mainloop.
//  - predsum folded into d_out (init = fc_b in prep; prev read from d_out).
//  - bias/w0/w1/fcW staged in smem (loaded pre-wait).
// W columns permuted: col n -> (unit n>>2, gate n&3), gate order i,f,g,o.
// h double-buffered across steps (cross-CTA race fix).
// ============================================================================

#define BATCH 2048
#define TT    32
#define HH    1024
#define N4    4096
#define KE    1024            // K = H (single fp16 term)
#define TM    128             // M tile
#define TN    128             // N tile
#define KC    64              // K chunk (fp16) = 128 bytes
#define NCH   (KE / KC)       // 16
#define NTHREADS 256
#define STAGES 3
#define STAGE_BYTES 32768     // A 16KB + B 16KB
#define STAGING_BYTES 2048
#define SMEM_BYTES  (1024 + STAGES * STAGE_BYTES + STAGING_BYTES)  // ~99KB
#define GPITCH 132            // gates smem pitch (floats), conflict-free

// Scratch (device globals; no allocation allowed)
__device__ __align__(256) __half g_Wext[(size_t)N4 * KE];        // 8 MB
__device__ __align__(256) __half g_Aext[2][(size_t)BATCH * KE];  // 2 x 4 MB
__device__ __align__(256) float g_c[(size_t)BATCH * HH];         // 8 MB
__device__ __align__(256) float g_bias[N4];
__device__ __align__(256) float g_w0[N4];
__device__ __align__(256) float g_w1[N4];
__device__ __align__(256) float g_fcW[HH];

// ---------------------------------------------------------------------------
// helpers
// ---------------------------------------------------------------------------
__device__ __forceinline__ uint32_t smem_u32(const void* p) {
    uint32_t a;
    asm("{ .reg .u64 t; cvta.to.shared.u64 t, %1; cvt.u32.u64 %0, t; }" : "=r"(a) : "l"(p));
    return a;
}
__device__ __forceinline__ void cp_async16(uint32_t dst, const void* src) {
    asm volatile("cp.async.cg.shared.global [%0], [%1], 16;" :: "r"(dst), "l"(src) : "memory");
}
__device__ __forceinline__ void cp_commit() {
    asm volatile("cp.async.commit_group;" ::: "memory");
}
__device__ __forceinline__ uint32_t sw128(uint32_t off) {
    return off ^ ((off >> 3) & 0x70u);
}
__device__ __forceinline__ void ldsm_x4(uint32_t& r0, uint32_t& r1, uint32_t& r2, uint32_t& r3,
                                        uint32_t addr) {
    asm volatile("ldmatrix.sync.aligned.m8n8.x4.shared.b16 {%0,%1,%2,%3}, [%4];"
                 : "=r"(r0), "=r"(r1), "=r"(r2), "=r"(r3) : "r"(addr));
}
__device__ __forceinline__ void mma_fp16(float* d, const uint32_t* a, const uint32_t* b) {
    asm volatile(
        "mma.sync.aligned.m16n8k16.row.col.f32.f16.f16.f32 "
        "{%0,%1,%2,%3}, {%4,%5,%6,%7}, {%8,%9}, {%0,%1,%2,%3};"
        : "+f"(d[0]), "+f"(d[1]), "+f"(d[2]), "+f"(d[3])
        : "r"(a[0]), "r"(a[1]), "r"(a[2]), "r"(a[3]), "r"(b[0]), "r"(b[1]));
}
__device__ __forceinline__ float sigf(float x) {
    return __fdividef(1.0f, 1.0f + __expf(-x));
}
__device__ __forceinline__ float tanh_f(float x) {
    float xc = fminf(fmaxf(x, -15.0f), 15.0f);
    float e = __expf(2.0f * xc);
    return 1.0f - __fdividef(2.0f, e + 1.0f);
}

// ---------------------------------------------------------------------------
// Prep kernels
// ---------------------------------------------------------------------------
__global__ void prep_weights(const float* __restrict__ W_hh, const float* __restrict__ W_ih,
                             const float* __restrict__ b_ih, const float* __restrict__ b_hh,
                             const float* __restrict__ fc_W) {
    int idx = blockIdx.x * blockDim.x + threadIdx.x;   // 0 .. 4096*1024-1
    int n = idx >> 10, k = idx & 1023;
    int r = (n & 3) * HH + (n >> 2);                   // col n -> orig W_hh row
    g_Wext[(size_t)n * KE + k] = __float2half(W_hh[(size_t)r * HH + k]);
    if (idx < N4) {
        int rr = (idx & 3) * HH + (idx >> 2);
        g_bias[idx] = b_ih[rr] + b_hh[rr];
        g_w0[idx] = W_ih[rr * 2 + 0];
        g_w1[idx] = W_ih[rr * 2 + 1];
    }
    if (idx < HH) g_fcW[idx] = fc_W[idx];
}

__global__ void prep_state(const float* __restrict__ hidden, const float* __restrict__ cell,
                           float* __restrict__ out, const float* __restrict__ fc_b) {
    int idx = blockIdx.x * blockDim.x + threadIdx.x;   // 0 .. 2048*1024-1
    g_c[idx] = cell[idx];
    g_Aext[0][idx] = __float2half(hidden[idx]);
    if (idx < BATCH * TT) out[idx] = fc_b[0];          // predsum accumulates on top
}

// ---------------------------------------------------------------------------
// Step kernel: GEMM (tile 128x128, K=1024) + fused LSTM cell epilogue
// 256 threads = 8 warps; warp tile 64x32: warp_m = wid&1, warp_n = wid>>1.
// ---------------------------------------------------------------------------
__global__ void __launch_bounds__(NTHREADS, 2)
step_kernel(int t, const float* __restrict__ future_fd, float* __restrict__ out) {
    const __half* __restrict__ Asrc = g_Aext[t & 1];
    __half* __restrict__ Adst = g_Aext[(t + 1) & 1];

    extern __shared__ char smem_raw[];
    uint32_t sb = smem_u32(smem_raw);
    uint32_t ab = (sb + 1023u) & ~1023u;
    char* smem = smem_raw + (ab - sb);
    const uint32_t tiles = ab;

    const int tid = threadIdx.x;
    const int wid = tid >> 5;
    const int lid = tid & 31;
    const int wm = wid & 1;          // 0..1  (64-row block)
    const int wn = wid >> 1;         // 0..3  (32-col block)
    const int m0 = blockIdx.x * TM;
    const int n0 = blockIdx.y * TN;
    const int u0 = n0 >> 2;          // first unit of this CTA (32 units)

    // ---- const staging (step-invariant: safe pre-wait) ---------------------
    float4* smB  = (float4*)(smem + STAGES * STAGE_BYTES);   // [32]
    float4* smW0 = smB + 32;
    float4* smW1 = smB + 64;
    float*  smFc = (float*)(smB + 96);                        // [32]
    if (tid < 32)        smB[tid]        = ((const float4*)g_bias)[u0 + tid];
    else if (tid < 64)   smW0[tid - 32]  = ((const float4*)g_w0)[u0 + tid - 32];
    else if (tid < 96)   smW1[tid - 64]  = ((const float4*)g_w1)[u0 + tid - 64];
    else if (tid < 128)  smFc[tid - 96]  = g_fcW[u0 + tid - 96];

    // ---- split chunk loaders ----------------------------------------------
    // A: 128 rows x 128B (h, step-dependent). B: 128 rows x 128B (weights).
    auto load_A = [&](int c, int s) {
        const int k0 = c * KC;
        const uint32_t base = tiles + s * STAGE_BYTES;
        #pragma unroll
        for (int j = 0; j < 4; j++) {
            int li = tid + j * NTHREADS;
            int ri = li >> 3, q = li & 7;
            uint32_t dst = base + sw128((uint32_t)(ri * 128 + q * 16));
            cp_async16(dst, Asrc + ((size_t)(m0 + ri) * KE + k0 + q * 8));
        }
    };
    auto load_B = [&](int c, int s) {
        const int k0 = c * KC;
        const uint32_t base = tiles + s * STAGE_BYTES + 16384;
        #pragma unroll
        for (int j = 0; j < 4; j++) {
            int li = tid + j * NTHREADS;
            int ri = li >> 3, q = li & 7;
            uint32_t dst = base + sw128((uint32_t)(ri * 128 + q * 16));
            cp_async16(dst, g_Wext + ((size_t)(n0 + ri) * KE + k0 + q * 8));
        }
    };

    // ---- PDL prologue: weights prefetch overlaps prior step's tail ---------
    load_B(0, 0); cp_commit();                 // group: B0
    load_B(1, 1); cp_commit();                 // group: B1
    asm volatile("griddepcontrol.wait;" ::: "memory");
    load_A(0, 0); cp_commit();                 // group: A0
    load_A(1, 1); cp_commit();                 // group: A1

    // ---- lane constants for ldmatrix addressing ----------------------------
    const int a_lr = lid & 15;
    const int a_ch = (lid >> 4) << 4;
    const int b_nr = (lid & 7) + ((lid >> 4) << 3);
    const int b_ch = ((lid >> 3) & 1) << 4;

    float acc[4][4][4];
    #pragma unroll
    for (int i = 0; i < 4; i++)
        #pragma unroll
        for (int j = 0; j < 4; j++)
            #pragma unroll
            for (int r = 0; r < 4; r++) acc[i][j][r] = 0.0f;

    #pragma unroll 1
    for (int c = 0; c < NCH; c++) {
        // iter 0: groups {B0,B1,A0,A1}; wait_group 1 retires B0,B1,A0 -> stage0 ready.
        // steady state: wait_group 1 retires chunk c; chunk c+1 may be in flight.
        if (c < NCH - 2) asm volatile("cp.async.wait_group 1;" ::: "memory");
        else             asm volatile("cp.async.wait_group 0;" ::: "memory");
        __syncthreads();

        if (c + 2 < NCH) { load_A(c + 2, (c + 2) % STAGES); load_B(c + 2, (c + 2) % STAGES); cp_commit(); }

        const uint32_t As = tiles + (c % STAGES) * STAGE_BYTES;
        const uint32_t Bs = As + 16384;

        #pragma unroll
        for (int ks = 0; ks < 4; ks++) {
            uint32_t a[4][4], b[4][2];
            #pragma unroll
            for (int mi = 0; mi < 4; mi++) {
                uint32_t off = (uint32_t)((wm * 64 + mi * 16 + a_lr) * 128 + ks * 32 + a_ch);
                ldsm_x4(a[mi][0], a[mi][1], a[mi][2], a[mi][3], As + sw128(off));
            }
            #pragma unroll
            for (int nb = 0; nb < 2; nb++) {
                uint32_t off = (uint32_t)((wn * 32 + nb * 16 + b_nr) * 128 + ks * 32 + b_ch);
                ldsm_x4(b[nb * 2][0], b[nb * 2][1], b[nb * 2 + 1][0], b[nb * 2 + 1][1],
                        Bs + sw128(off));
            }
            #pragma unroll
            for (int mi = 0; mi < 4; mi++)
                #pragma unroll
                for (int j = 0; j < 4; j++)
                    mma_fp16(acc[mi][j], a[mi], b[j]);
        }
    }
    __syncthreads();   // smem stages now reusable as epilogue scratch

    // Allow next step's CTAs to spin up and prefetch weights while we run
    // the epilogue (their A loads wait on griddepcontrol.wait).
    asm volatile("griddepcontrol.launch_dependents;");

    // ---- epilogue: gates -> smem, fused cell update ------------------------
    float* gates = (float*)smem;                  // 128 rows x GPITCH floats
    const int g = lid >> 2, tg = lid & 3;

    {
        const int clb = wn * 32;
        #pragma unroll
        for (int mi = 0; mi < 4; mi++) {
            const int r = wm * 64 + mi * 16 + g;
            #pragma unroll
            for (int j = 0; j < 4; j++) {
                const int cl = clb + j * 8 + 2 * tg;
                *(float2*)&gates[r * GPITCH + cl]       = make_float2(acc[mi][j][0], acc[mi][j][1]);
                *(float2*)&gates[(r + 8) * GPITCH + cl] = make_float2(acc[mi][j][2], acc[mi][j][3]);
            }
        }
    }
    __syncthreads();

    #pragma unroll 2
    for (int jj = 0; jj < 16; jj++) {
        const int idx = tid + jj * NTHREADS;       // 4096 = 128 rows x 32 units
        const int row = idx >> 5, u = idx & 31;
        const int ug = u0 + u;                     // global unit 0..1023
        const int b = m0 + row;

        float4 gv = *(float4*)&gates[row * GPITCH + 4 * u];
        float4 bs = smB[u];
        float4 w0 = smW0[u];
        float4 w1 = smW1[u];

        float prev = (t > 0) ? out[b * TT + (t - 1)] : 0.0f;   // includes fc_b
        const float fdv = future_fd[b * TT + t];

        float gi = gv.x + bs.x + prev * w0.x + fdv * w1.x;
        float gf = gv.y + bs.y + prev * w0.y + fdv * w1.y;
        float gg = gv.z + bs.z + prev * w0.z + fdv * w1.z;
        float go = gv.w + bs.w + prev * w0.w + fdv * w1.w;

        float co = g_c[(size_t)b * HH + ug];
        float cn = sigf(gf) * co + sigf(gi) * tanh_f(gg);
        float h  = sigf(go) * tanh_f(cn);
        g_c[(size_t)b * HH + ug] = cn;
        Adst[(size_t)b * KE + ug] = __float2half(h);

        float fcp = h * smFc[u];
        #pragma unroll
        for (int o = 16; o; o >>= 1) fcp += __shfl_down_sync(0xFFFFFFFFu, fcp, o);
        if (lid == 0) atomicAdd(&out[b * TT + t], fcp);
    }
}

// ---------------------------------------------------------------------------
// Host launcher
// ---------------------------------------------------------------------------
extern "C" void kernel_launch(void* const* d_in, const int* in_sizes, int n_in,
                              void* d_out, int out_size) {
    const float* future_fd = (const float*)d_in[0];
    const float* hidden    = (const float*)d_in[1];
    const float* cell      = (const float*)d_in[2];
    const float* W_ih      = (const float*)d_in[3];
    const float* W_hh      = (const float*)d_in[4];
    const float* b_ih      = (const float*)d_in[5];
    const float* b_hh      = (const float*)d_in[6];
    const float* fc_W      = (const float*)d_in[7];
    const float* fc_b      = (const float*)d_in[8];
    float* out = (float*)d_out;

    cudaFuncSetAttribute(step_kernel, cudaFuncAttributeMaxDynamicSharedMemorySize, SMEM_BYTES);

    prep_weights<<<(N4 * HH) / 256, 256>>>(W_hh, W_ih, b_ih, b_hh, fc_W);
    prep_state<<<(BATCH * HH) / 256, 256>>>(hidden, cell, out, fc_b);

    cudaLaunchAttribute pdl_attr;
    pdl_attr.id = cudaLaunchAttributeProgrammaticStreamSerialization;
    pdl_attr.val.programmaticStreamSerializationAllowed = 1;

    for (int t = 0; t < TT; t++) {
        cudaLaunchConfig_t cfg = {};
        cfg.gridDim = dim3(BATCH / TM, N4 / TN, 1);
        cfg.blockDim = dim3(NTHREADS, 1, 1);
        cfg.dynamicSmemBytes = SMEM_BYTES;
        cfg.stream = 0;
        if (t > 0) { cfg.attrs = &pdl_attr; cfg.numAttrs = 1; }   // t=0 plain: prep must fully finish
        cudaLaunchKernelEx(&cfg, step_kernel, t, future_fd, out);
    }
}